// round 4
// baseline (speedup 1.0000x reference)
#include <cuda_runtime.h>
#include <math.h>

#define Bb 4
#define Tt 2048
#define DMdim 768
#define DIdim 1536
#define Nn 64
#define DCv 4
#define Rr 48
#define MM (Bb*Tt)          /* 8192 rows */
#define PROJW (Rr + 2*Nn)   /* 176 */

// ---------------- scratch (device globals; no allocation allowed) -------------
__device__ float g_x[MM*DMdim];          // current residual stream
__device__ float g_xz[MM*2*DIdim];       // in_proj output
__device__ float g_uc[MM*DIdim];         // conv+silu output
__device__ float g_proj[MM*PROJW];       // x_proj output
__device__ float g_delta[MM*DIdim];      // softplus(dt proj)
__device__ float g_y[MM*DIdim];          // scan output
__device__ float g_h[MM*DMdim];          // out_proj output

// buffer ids: resolved in device code so kernel_launch makes NO runtime-API calls
#define BUF_X     0
#define BUF_XZ    1
#define BUF_UC    2
#define BUF_PROJ  3
#define BUF_DELTA 4
#define BUF_Y     5
#define BUF_H     6

__device__ __forceinline__ float* gbuf(int id) {
    switch (id) {
        case BUF_X:     return g_x;
        case BUF_XZ:    return g_xz;
        case BUF_UC:    return g_uc;
        case BUF_PROJ:  return g_proj;
        case BUF_DELTA: return g_delta;
        case BUF_Y:     return g_y;
        default:        return g_h;
    }
}

// ---------------- generic SGEMM: C[M,N] = A[M,K] * B[N,K]^T -------------------
#define BMt 128
#define BNt 64
#define BKt 16
#define BMP (BMt+4)
#define BNP (BNt+4)

__global__ __launch_bounds__(256) void sgemm_kernel(
    int aId, int lda,
    const float* __restrict__ Bm, int ldb,
    int cId, int ldc,
    int Md, int Nd, int Kd,
    const float* __restrict__ bias, int epi)
{
    const float* __restrict__ A = gbuf(aId);
    float* __restrict__ C = gbuf(cId);

    __shared__ float As[BKt*BMP];
    __shared__ float Bs[BKt*BNP];
    const int tid = threadIdx.x;
    const int m0 = blockIdx.y * BMt;
    const int n0 = blockIdx.x * BNt;
    const int tx = tid & 15;   // -> n
    const int ty = tid >> 4;   // -> m

    float acc[8][4];
#pragma unroll
    for (int i = 0; i < 8; i++)
#pragma unroll
        for (int j = 0; j < 4; j++) acc[i][j] = 0.f;

    for (int k0 = 0; k0 < Kd; k0 += BKt) {
        // A tile: 128 rows x 16 k = 512 float4 loads, 2 per thread
#pragma unroll
        for (int it = 0; it < 2; it++) {
            int e = tid + it * 256;
            int r = e >> 2;
            int kq = e & 3;
            int gm = m0 + r;
            float4 v = make_float4(0.f, 0.f, 0.f, 0.f);
            if (gm < Md) v = *(const float4*)&A[(size_t)gm * lda + k0 + kq * 4];
            As[(kq*4+0)*BMP + r] = v.x;
            As[(kq*4+1)*BMP + r] = v.y;
            As[(kq*4+2)*BMP + r] = v.z;
            As[(kq*4+3)*BMP + r] = v.w;
        }
        // B tile: 64 rows x 16 k = 256 float4 loads, 1 per thread
        {
            int r = tid >> 2;
            int kq = tid & 3;
            int gn = n0 + r;
            float4 v = make_float4(0.f, 0.f, 0.f, 0.f);
            if (gn < Nd) v = *(const float4*)&Bm[(size_t)gn * ldb + k0 + kq * 4];
            Bs[(kq*4+0)*BNP + r] = v.x;
            Bs[(kq*4+1)*BNP + r] = v.y;
            Bs[(kq*4+2)*BNP + r] = v.z;
            Bs[(kq*4+3)*BNP + r] = v.w;
        }
        __syncthreads();
#pragma unroll
        for (int k = 0; k < BKt; k++) {
            float4 a0 = *(float4*)&As[k*BMP + ty*8];
            float4 a1 = *(float4*)&As[k*BMP + ty*8 + 4];
            float4 b0 = *(float4*)&Bs[k*BNP + tx*4];
            float av[8] = {a0.x, a0.y, a0.z, a0.w, a1.x, a1.y, a1.z, a1.w};
            float bv[4] = {b0.x, b0.y, b0.z, b0.w};
#pragma unroll
            for (int i = 0; i < 8; i++)
#pragma unroll
                for (int j = 0; j < 4; j++)
                    acc[i][j] = fmaf(av[i], bv[j], acc[i][j]);
        }
        __syncthreads();
    }
#pragma unroll
    for (int i = 0; i < 8; i++) {
        int gm = m0 + ty*8 + i;
        if (gm >= Md) continue;
#pragma unroll
        for (int j = 0; j < 4; j++) {
            int gn = n0 + tx*4 + j;
            if (gn >= Nd) continue;
            float v = acc[i][j];
            if (epi == 1) {             // softplus(v + bias[n])
                v += bias[gn];
                v = (v > 20.f) ? v : log1pf(expf(v));
            }
            C[(size_t)gm * ldc + gn] = v;
        }
    }
}

// ---------------- mask multiply ----------------------------------------------
__global__ void mask_kernel(const float* __restrict__ x,
                            const float* __restrict__ mask)
{
    int idx = blockIdx.x * blockDim.x + threadIdx.x;
    if (idx >= MM*DMdim) return;
    int m = idx / DMdim;
    g_x[idx] = x[idx] * mask[m];
}

// ---------------- depthwise causal conv + silu -------------------------------
__global__ void conv_silu_kernel(const float* __restrict__ cw,
                                 const float* __restrict__ cb)
{
    int idx = blockIdx.x * blockDim.x + threadIdx.x;
    if (idx >= MM*DIdim) return;
    int d = idx % DIdim;
    int m = idx / DIdim;
    int t = m % Tt;
    float acc = cb[d];
    const float* w = cw + d * 4;
#pragma unroll
    for (int k = 0; k < 4; k++) {
        int tt = t - 3 + k;
        if (tt >= 0) acc = fmaf(g_xz[(size_t)(m - 3 + k) * (2*DIdim) + d], w[k], acc);
    }
    g_uc[idx] = acc / (1.f + __expf(-acc));   // silu
}

// ---------------- selective scan + D skip + z gate ---------------------------
// block = (d-tile of 32 channels, batch b); 256 threads = 32 d x 8 n-groups
__global__ __launch_bounds__(256) void scan_kernel(
    const float* __restrict__ A_log, const float* __restrict__ Dv)
{
    const int d0 = blockIdx.x * 32;
    const int b  = blockIdx.y;
    const int tid = threadIdx.x;
    const int dl = tid >> 3;     // 0..31: local d
    const int ng = tid & 7;      // 0..7 : n-group
    const int d  = d0 + dl;

    __shared__ float Bs[32*64];
    __shared__ float Cs[32*64];
    __shared__ float ds[32*32];
    __shared__ float us[32*32];
    __shared__ float zs[32*32];
    __shared__ float ysm[32*32];

    float h[8], ac[8];
#pragma unroll
    for (int j = 0; j < 8; j++) {
        h[j] = 0.f;
        ac[j] = -expf(A_log[d * Nn + ng + 8*j]);   // A = -exp(A_log), n = ng+8j
    }
    const float Dd = Dv[d];

    for (int c = 0; c < Tt/32; c++) {
        const int tbase = c * 32;
        // stage B,C (contiguous 128 floats per t, offset 48 in proj row)
#pragma unroll
        for (int j = 0; j < 16; j++) {
            int e = tid + j * 256;
            int t = e >> 7;
            int q = e & 127;
            float v = g_proj[(size_t)(b*Tt + tbase + t) * PROJW + Rr + q];
            if (q < 64) Bs[t*64 + q] = v;
            else        Cs[t*64 + (q - 64)] = v;
        }
        // stage delta, u, z (32 d contiguous per t)
#pragma unroll
        for (int j = 0; j < 4; j++) {
            int e = tid + j * 256;
            int t = e >> 5;
            int dd = e & 31;
            size_t row = (size_t)(b*Tt + tbase + t);
            ds[t*32 + dd] = g_delta[row * DIdim + d0 + dd];
            us[t*32 + dd] = g_uc[row * DIdim + d0 + dd];
            zs[t*32 + dd] = g_xz[row * (2*DIdim) + DIdim + d0 + dd];
        }
        __syncthreads();

        for (int t = 0; t < 32; t++) {
            float dv = ds[t*32 + dl];
            float coef = dv * us[t*32 + dl];
            float accv = 0.f;
#pragma unroll
            for (int j = 0; j < 8; j++) {
                int n = ng + 8*j;
                float e = __expf(dv * ac[j]);
                h[j] = fmaf(h[j], e, coef * Bs[t*64 + n]);
                accv = fmaf(h[j], Cs[t*64 + n], accv);
            }
            accv += __shfl_down_sync(0xffffffffu, accv, 4, 8);
            accv += __shfl_down_sync(0xffffffffu, accv, 2, 8);
            accv += __shfl_down_sync(0xffffffffu, accv, 1, 8);
            if (ng == 0) {
                float yv = accv + us[t*32 + dl] * Dd;
                float z = zs[t*32 + dl];
                yv *= z / (1.f + __expf(-z));   // * silu(z)
                ysm[t*32 + dl] = yv;
            }
        }
        __syncthreads();
#pragma unroll
        for (int j = 0; j < 4; j++) {
            int e = tid + j * 256;
            int t = e >> 5;
            int dd = e & 31;
            g_y[(size_t)(b*Tt + tbase + t) * DIdim + d0 + dd] = ysm[t*32 + dd];
        }
        __syncthreads();
    }
}

// ---------------- layernorm + film + residual --------------------------------
// reads g_h (mamba out) and g_x (residual); writes g_x (toX=1) or ext (toX=0)
__global__ __launch_bounds__(256) void ln_film_kernel(
    const float* __restrict__ lnw, const float* __restrict__ lnb,
    const float* __restrict__ fg, const float* __restrict__ fb,
    float* __restrict__ extOut, int toX)
{
    const int m = blockIdx.x;
    const int tid = threadIdx.x;
    const float* row = g_h + (size_t)m * DMdim;

    __shared__ float red[8];
    __shared__ float stats[2];

    float v[3];
    float s = 0.f;
#pragma unroll
    for (int j = 0; j < 3; j++) { v[j] = row[tid + j*256]; s += v[j]; }
#pragma unroll
    for (int o = 16; o > 0; o >>= 1) s += __shfl_down_sync(0xffffffffu, s, o);
    if ((tid & 31) == 0) red[tid >> 5] = s;
    __syncthreads();
    if (tid == 0) {
        float tot = 0.f;
        for (int i = 0; i < 8; i++) tot += red[i];
        stats[0] = tot;
    }
    __syncthreads();
    const float mean = stats[0] * (1.f / DMdim);

    float s2 = 0.f;
#pragma unroll
    for (int j = 0; j < 3; j++) { float dd = v[j] - mean; s2 += dd*dd; }
#pragma unroll
    for (int o = 16; o > 0; o >>= 1) s2 += __shfl_down_sync(0xffffffffu, s2, o);
    if ((tid & 31) == 0) red[tid >> 5] = s2;
    __syncthreads();
    if (tid == 0) {
        float tot = 0.f;
        for (int i = 0; i < 8; i++) tot += red[i];
        stats[1] = tot;
    }
    __syncthreads();
    const float rstd = rsqrtf(stats[1] * (1.f / DMdim) + 1e-5f);

    float* outp = toX ? g_x : extOut;
#pragma unroll
    for (int j = 0; j < 3; j++) {
        int c = tid + j*256;
        size_t gi = (size_t)m * DMdim + c;
        float hn = (v[j] - mean) * rstd * lnw[c] + lnb[c];
        outp[gi] = fg[gi] * hn + fb[gi] + g_x[gi];
    }
}

// ---------------- driver ------------------------------------------------------
extern "C" void kernel_launch(void* const* d_in, const int* in_sizes, int n_in,
                              void* d_out, int out_size)
{
    const float* x    = (const float*)d_in[0];
    const float* mask = (const float*)d_in[1];
    const float* fg   = (const float*)d_in[2];
    const float* fb   = (const float*)d_in[3];
    const float* Win  = (const float*)d_in[4];
    const float* cw   = (const float*)d_in[5];
    const float* cb   = (const float*)d_in[6];
    const float* Wx   = (const float*)d_in[7];
    const float* Wdt  = (const float*)d_in[8];
    const float* bdt  = (const float*)d_in[9];
    const float* Alog = (const float*)d_in[10];
    const float* Dv   = (const float*)d_in[11];
    const float* Wout = (const float*)d_in[12];
    const float* lnw  = (const float*)d_in[13];
    const float* lnb  = (const float*)d_in[14];
    float* out = (float*)d_out;

    mask_kernel<<<(MM*DMdim + 255)/256, 256>>>(x, mask);

    for (int i = 0; i < 2; i++) {
        const float* Win_i  = Win  + (size_t)i * (2*DIdim) * DMdim;
        const float* cw_i   = cw   + (size_t)i * DIdim * DCv;
        const float* cb_i   = cb   + (size_t)i * DIdim;
        const float* Wx_i   = Wx   + (size_t)i * PROJW * DIdim;
        const float* Wdt_i  = Wdt  + (size_t)i * DIdim * Rr;
        const float* bdt_i  = bdt  + (size_t)i * DIdim;
        const float* Alog_i = Alog + (size_t)i * DIdim * Nn;
        const float* Dv_i   = Dv   + (size_t)i * DIdim;
        const float* Wout_i = Wout + (size_t)i * DMdim * DIdim;
        const float* lnw_i  = lnw  + (size_t)i * DMdim;
        const float* lnb_i  = lnb  + (size_t)i * DMdim;
        const float* fg_i   = fg   + (size_t)i * MM * DMdim;
        const float* fb_i   = fb   + (size_t)i * MM * DMdim;

        // in_proj: (8192,768) x (3072,768)^T -> (8192,3072)
        sgemm_kernel<<<dim3((2*DIdim)/BNt, MM/BMt), 256>>>(
            BUF_X, DMdim, Win_i, DMdim, BUF_XZ, 2*DIdim, MM, 2*DIdim, DMdim, (const float*)0, 0);

        conv_silu_kernel<<<(MM*DIdim + 255)/256, 256>>>(cw_i, cb_i);

        // x_proj: (8192,1536) x (176,1536)^T -> (8192,176)
        sgemm_kernel<<<dim3((PROJW + BNt - 1)/BNt, MM/BMt), 256>>>(
            BUF_UC, DIdim, Wx_i, DIdim, BUF_PROJ, PROJW, MM, PROJW, DIdim, (const float*)0, 0);

        // dt_proj + softplus: (8192,48) x (1536,48)^T -> (8192,1536)
        sgemm_kernel<<<dim3(DIdim/BNt, MM/BMt), 256>>>(
            BUF_PROJ, PROJW, Wdt_i, Rr, BUF_DELTA, DIdim, MM, DIdim, Rr, bdt_i, 1);

        scan_kernel<<<dim3(DIdim/32, Bb), 256>>>(Alog_i, Dv_i);

        // out_proj: (8192,1536) x (768,1536)^T -> (8192,768)
        sgemm_kernel<<<dim3(DMdim/BNt, MM/BMt), 256>>>(
            BUF_Y, DIdim, Wout_i, DIdim, BUF_H, DMdim, MM, DMdim, DIdim, (const float*)0, 0);

        ln_film_kernel<<<MM, 256>>>(lnw_i, lnb_i, fg_i, fb_i, out, (i == 1) ? 0 : 1);
    }
}

// round 7
// speedup vs baseline: 1.3826x; 1.3826x over previous
#include <cuda_runtime.h>
#include <cuda_bf16.h>
#include <math.h>
#include <stdint.h>

#define Bb 4
#define Tt 2048
#define DMdim 768
#define DIdim 1536
#define Nn 64
#define DCv 4
#define Rr 48
#define MM (Bb*Tt)          /* 8192 rows */
#define PROJW (Rr + 2*Nn)   /* 176 */

// ---------------- scratch (device globals; no allocation allowed) -------------
__device__ float g_x[MM*DMdim];
__device__ float g_xz[MM*2*DIdim];
__device__ float g_uc[MM*DIdim];
__device__ float g_proj[MM*PROJW];
__device__ float g_delta[MM*DIdim];
__device__ float g_y[MM*DIdim];
__device__ float g_h[MM*DMdim];

#define BUF_X     0
#define BUF_XZ    1
#define BUF_UC    2
#define BUF_PROJ  3
#define BUF_DELTA 4
#define BUF_Y     5
#define BUF_H     6

__device__ __forceinline__ float* gbuf(int id) {
    switch (id) {
        case BUF_X:     return g_x;
        case BUF_XZ:    return g_xz;
        case BUF_UC:    return g_uc;
        case BUF_PROJ:  return g_proj;
        case BUF_DELTA: return g_delta;
        case BUF_Y:     return g_y;
        default:        return g_h;
    }
}

__device__ __forceinline__ uint32_t smem_u32(const void* p) {
    uint32_t a;
    asm("{ .reg .u64 t; cvta.to.shared.u64 t, %1; cvt.u32.u64 %0, t; }"
        : "=r"(a) : "l"(p));
    return a;
}

__device__ __forceinline__ void ldsm4(uint32_t* r, uint32_t addr) {
    asm volatile("ldmatrix.sync.aligned.m8n8.x4.shared.b16 {%0,%1,%2,%3}, [%4];"
        : "=r"(r[0]), "=r"(r[1]), "=r"(r[2]), "=r"(r[3]) : "r"(addr));
}

__device__ __forceinline__ void mma_bf16(float* c, const uint32_t* a, const uint32_t* b) {
    asm volatile(
        "mma.sync.aligned.m16n8k16.row.col.f32.bf16.bf16.f32 "
        "{%0,%1,%2,%3}, {%4,%5,%6,%7}, {%8,%9}, {%0,%1,%2,%3};"
        : "+f"(c[0]), "+f"(c[1]), "+f"(c[2]), "+f"(c[3])
        : "r"(a[0]), "r"(a[1]), "r"(a[2]), "r"(a[3]), "r"(b[0]), "r"(b[1]));
}

// ---------------- HMMA split-bf16 GEMM: C[M,N] = A[M,K] * W[N,K]^T -----------
// CTA tile 128x128, K-chunk 32 bf16, 8 warps (2x4), warp tile 64x32.
// A = Ah + Al (bf16 hi + residual); C += Ah*Bh + Al*Bh + Ah*Bl.
#define TPAD 40   /* padded SMEM row stride in bf16 elems (80B, ldmatrix conflict-free) */

__global__ __launch_bounds__(256, 1) void tgemm_kernel(
    int aId, int lda, const float* __restrict__ W, int ldb,
    int cId, int ldc, int Nd, int Kd)
{
    __shared__ __nv_bfloat16 sAh[128*TPAD], sAl[128*TPAD];
    __shared__ __nv_bfloat16 sBh[128*TPAD], sBl[128*TPAD];

    const float* __restrict__ A = gbuf(aId);
    float* __restrict__ C = gbuf(cId);

    const int tid  = threadIdx.x;
    const int lane = tid & 31;
    const int wid  = tid >> 5;
    const int wm   = (wid & 1) * 64;    // warp m offset in tile
    const int wn   = (wid >> 1) * 32;   // warp n offset in tile
    const int m0   = blockIdx.y * 128;
    const int n0   = blockIdx.x * 128;

    float acc[4][4][4];
#pragma unroll
    for (int i = 0; i < 4; i++)
#pragma unroll
        for (int j = 0; j < 4; j++)
#pragma unroll
            for (int k = 0; k < 4; k++) acc[i][j][k] = 0.f;

    // ---- precompute ldmatrix lane addresses
    const int g  = lane >> 3;   // 8x8 tile selector within x4
    const int lr = lane & 7;    // row within 8x8 tile
    uint32_t aAh[4], aAl[4];
#pragma unroll
    for (int mt = 0; mt < 4; mt++) {
        // A m16k16 tile: T0 rows0-7 k0 | T1 rows8-15 k0 | T2 rows0-7 k8 | T3 rows8-15 k8
        int row = wm + mt*16 + (g & 1)*8 + lr;
        int off = row * TPAD + (g >> 1)*8;
        aAh[mt] = smem_u32(&sAh[off]);
        aAl[mt] = smem_u32(&sAl[off]);
    }
    uint32_t aBh[2], aBl[2];
#pragma unroll
    for (int p = 0; p < 2; p++) {
        // B pair of n8k16 tiles: T0 n0-7 k0 | T1 n0-7 k8 | T2 n8-15 k0 | T3 n8-15 k8
        int rown = wn + p*16 + (g >> 1)*8 + lr;
        int off = rown * TPAD + (g & 1)*8;
        aBh[p] = smem_u32(&sBh[off]);
        aBl[p] = smem_u32(&sBl[off]);
    }

    for (int k0 = 0; k0 < Kd; k0 += 32) {
        __syncthreads();
        // ---- stage A tile (128 rows x 32 k) fp32 -> bf16 hi/lo
#pragma unroll
        for (int i = 0; i < 4; i++) {
            int e = tid + (i << 8);
            int r = e >> 3, q = e & 7;
            float4 v = *(const float4*)&A[(size_t)(m0 + r) * lda + k0 + q * 4];
            __nv_bfloat162 h0 = __float22bfloat162_rn(make_float2(v.x, v.y));
            __nv_bfloat162 h1 = __float22bfloat162_rn(make_float2(v.z, v.w));
            __nv_bfloat162 l0 = __float22bfloat162_rn(make_float2(
                v.x - __bfloat162float(h0.x), v.y - __bfloat162float(h0.y)));
            __nv_bfloat162 l1 = __float22bfloat162_rn(make_float2(
                v.z - __bfloat162float(h1.x), v.w - __bfloat162float(h1.y)));
            int idx = r * TPAD + q * 4;
            *(__nv_bfloat162*)&sAh[idx]     = h0;
            *(__nv_bfloat162*)&sAh[idx + 2] = h1;
            *(__nv_bfloat162*)&sAl[idx]     = l0;
            *(__nv_bfloat162*)&sAl[idx + 2] = l1;
        }
        // ---- stage B tile (128 N-rows x 32 k) with N guard
#pragma unroll
        for (int i = 0; i < 4; i++) {
            int e = tid + (i << 8);
            int r = e >> 3, q = e & 7;
            int gn = n0 + r;
            float4 v = make_float4(0.f, 0.f, 0.f, 0.f);
            if (gn < Nd) v = *(const float4*)&W[(size_t)gn * ldb + k0 + q * 4];
            __nv_bfloat162 h0 = __float22bfloat162_rn(make_float2(v.x, v.y));
            __nv_bfloat162 h1 = __float22bfloat162_rn(make_float2(v.z, v.w));
            __nv_bfloat162 l0 = __float22bfloat162_rn(make_float2(
                v.x - __bfloat162float(h0.x), v.y - __bfloat162float(h0.y)));
            __nv_bfloat162 l1 = __float22bfloat162_rn(make_float2(
                v.z - __bfloat162float(h1.x), v.w - __bfloat162float(h1.y)));
            int idx = r * TPAD + q * 4;
            *(__nv_bfloat162*)&sBh[idx]     = h0;
            *(__nv_bfloat162*)&sBh[idx + 2] = h1;
            *(__nv_bfloat162*)&sBl[idx]     = l0;
            *(__nv_bfloat162*)&sBl[idx + 2] = l1;
        }
        __syncthreads();

#pragma unroll
        for (int ks = 0; ks < 2; ks++) {
            uint32_t ah[4][4], al[4][4], bh[4][2], bl[4][2];
#pragma unroll
            for (int mt = 0; mt < 4; mt++) {
                ldsm4(ah[mt], aAh[mt] + ks * 32);
                ldsm4(al[mt], aAl[mt] + ks * 32);
            }
#pragma unroll
            for (int p = 0; p < 2; p++) {
                uint32_t t[4];
                ldsm4(t, aBh[p] + ks * 32);
                bh[2*p][0] = t[0]; bh[2*p][1] = t[1];
                bh[2*p+1][0] = t[2]; bh[2*p+1][1] = t[3];
                ldsm4(t, aBl[p] + ks * 32);
                bl[2*p][0] = t[0]; bl[2*p][1] = t[1];
                bl[2*p+1][0] = t[2]; bl[2*p+1][1] = t[3];
            }
#pragma unroll
            for (int mt = 0; mt < 4; mt++)
#pragma unroll
                for (int nt = 0; nt < 4; nt++) {
                    mma_bf16(acc[mt][nt], ah[mt], bh[nt]);
                    mma_bf16(acc[mt][nt], al[mt], bh[nt]);
                    mma_bf16(acc[mt][nt], ah[mt], bl[nt]);
                }
        }
    }

    // ---- epilogue
#pragma unroll
    for (int mt = 0; mt < 4; mt++) {
#pragma unroll
        for (int nt = 0; nt < 4; nt++) {
            int row = m0 + wm + mt*16 + (lane >> 2);
            int col = n0 + wn + nt*8 + (lane & 3)*2;
            if (col < Nd) {
                *(float2*)&C[(size_t)row * ldc + col] =
                    make_float2(acc[mt][nt][0], acc[mt][nt][1]);
                *(float2*)&C[(size_t)(row + 8) * ldc + col] =
                    make_float2(acc[mt][nt][2], acc[mt][nt][3]);
            }
        }
    }
}

// ---------------- fp32 SGEMM (kept for dt_proj, K=48) ------------------------
#define BMt 128
#define BNt 64
#define BKt 16
#define BMP (BMt+4)
#define BNP (BNt+4)

__global__ __launch_bounds__(256) void sgemm_kernel(
    int aId, int lda, const float* __restrict__ Bm, int ldb,
    int cId, int ldc, int Md, int Nd, int Kd,
    const float* __restrict__ bias, int epi)
{
    const float* __restrict__ A = gbuf(aId);
    float* __restrict__ C = gbuf(cId);

    __shared__ float As[BKt*BMP];
    __shared__ float Bs[BKt*BNP];
    const int tid = threadIdx.x;
    const int m0 = blockIdx.y * BMt;
    const int n0 = blockIdx.x * BNt;
    const int tx = tid & 15;
    const int ty = tid >> 4;

    float acc[8][4];
#pragma unroll
    for (int i = 0; i < 8; i++)
#pragma unroll
        for (int j = 0; j < 4; j++) acc[i][j] = 0.f;

    for (int k0 = 0; k0 < Kd; k0 += BKt) {
#pragma unroll
        for (int it = 0; it < 2; it++) {
            int e = tid + it * 256;
            int r = e >> 2;
            int kq = e & 3;
            int gm = m0 + r;
            float4 v = make_float4(0.f, 0.f, 0.f, 0.f);
            if (gm < Md) v = *(const float4*)&A[(size_t)gm * lda + k0 + kq * 4];
            As[(kq*4+0)*BMP + r] = v.x;
            As[(kq*4+1)*BMP + r] = v.y;
            As[(kq*4+2)*BMP + r] = v.z;
            As[(kq*4+3)*BMP + r] = v.w;
        }
        {
            int r = tid >> 2;
            int kq = tid & 3;
            int gn = n0 + r;
            float4 v = make_float4(0.f, 0.f, 0.f, 0.f);
            if (gn < Nd) v = *(const float4*)&Bm[(size_t)gn * ldb + k0 + kq * 4];
            Bs[(kq*4+0)*BNP + r] = v.x;
            Bs[(kq*4+1)*BNP + r] = v.y;
            Bs[(kq*4+2)*BNP + r] = v.z;
            Bs[(kq*4+3)*BNP + r] = v.w;
        }
        __syncthreads();
#pragma unroll
        for (int k = 0; k < BKt; k++) {
            float4 a0 = *(float4*)&As[k*BMP + ty*8];
            float4 a1 = *(float4*)&As[k*BMP + ty*8 + 4];
            float4 b0 = *(float4*)&Bs[k*BNP + tx*4];
            float av[8] = {a0.x, a0.y, a0.z, a0.w, a1.x, a1.y, a1.z, a1.w};
            float bv[4] = {b0.x, b0.y, b0.z, b0.w};
#pragma unroll
            for (int i = 0; i < 8; i++)
#pragma unroll
                for (int j = 0; j < 4; j++)
                    acc[i][j] = fmaf(av[i], bv[j], acc[i][j]);
        }
        __syncthreads();
    }
#pragma unroll
    for (int i = 0; i < 8; i++) {
        int gm = m0 + ty*8 + i;
        if (gm >= Md) continue;
#pragma unroll
        for (int j = 0; j < 4; j++) {
            int gn = n0 + tx*4 + j;
            if (gn >= Nd) continue;
            float v = acc[i][j];
            if (epi == 1) {
                v += bias[gn];
                v = (v > 20.f) ? v : log1pf(expf(v));
            }
            C[(size_t)gm * ldc + gn] = v;
        }
    }
}

// ---------------- mask multiply ----------------------------------------------
__global__ void mask_kernel(const float* __restrict__ x,
                            const float* __restrict__ mask)
{
    int idx = blockIdx.x * blockDim.x + threadIdx.x;
    if (idx >= MM*DMdim) return;
    int m = idx / DMdim;
    g_x[idx] = x[idx] * mask[m];
}

// ---------------- depthwise causal conv + silu -------------------------------
__global__ void conv_silu_kernel(const float* __restrict__ cw,
                                 const float* __restrict__ cb)
{
    int idx = blockIdx.x * blockDim.x + threadIdx.x;
    if (idx >= MM*DIdim) return;
    int d = idx % DIdim;
    int m = idx / DIdim;
    int t = m % Tt;
    float acc = cb[d];
    const float* w = cw + d * 4;
#pragma unroll
    for (int k = 0; k < 4; k++) {
        int tt = t - 3 + k;
        if (tt >= 0) acc = fmaf(g_xz[(size_t)(m - 3 + k) * (2*DIdim) + d], w[k], acc);
    }
    g_uc[idx] = acc / (1.f + __expf(-acc));
}

// ---------------- selective scan + D skip + z gate ---------------------------
__global__ __launch_bounds__(256) void scan_kernel(
    const float* __restrict__ A_log, const float* __restrict__ Dv)
{
    const int d0 = blockIdx.x * 32;
    const int b  = blockIdx.y;
    const int tid = threadIdx.x;
    const int dl = tid >> 3;
    const int ng = tid & 7;
    const int d  = d0 + dl;

    __shared__ float Bs[32*64];
    __shared__ float Cs[32*64];
    __shared__ float ds[32*32];
    __shared__ float us[32*32];
    __shared__ float zs[32*32];
    __shared__ float ysm[32*32];

    float h[8], ac[8];
#pragma unroll
    for (int j = 0; j < 8; j++) {
        h[j] = 0.f;
        ac[j] = -expf(A_log[d * Nn + ng + 8*j]);
    }
    const float Dd = Dv[d];

    for (int c = 0; c < Tt/32; c++) {
        const int tbase = c * 32;
#pragma unroll
        for (int j = 0; j < 16; j++) {
            int e = tid + j * 256;
            int t = e >> 7;
            int q = e & 127;
            float v = g_proj[(size_t)(b*Tt + tbase + t) * PROJW + Rr + q];
            if (q < 64) Bs[t*64 + q] = v;
            else        Cs[t*64 + (q - 64)] = v;
        }
#pragma unroll
        for (int j = 0; j < 4; j++) {
            int e = tid + j * 256;
            int t = e >> 5;
            int dd = e & 31;
            size_t row = (size_t)(b*Tt + tbase + t);
            ds[t*32 + dd] = g_delta[row * DIdim + d0 + dd];
            us[t*32 + dd] = g_uc[row * DIdim + d0 + dd];
            zs[t*32 + dd] = g_xz[row * (2*DIdim) + DIdim + d0 + dd];
        }
        __syncthreads();

        for (int t = 0; t < 32; t++) {
            float dv = ds[t*32 + dl];
            float coef = dv * us[t*32 + dl];
            float accv = 0.f;
#pragma unroll
            for (int j = 0; j < 8; j++) {
                int n = ng + 8*j;
                float e = __expf(dv * ac[j]);
                h[j] = fmaf(h[j], e, coef * Bs[t*64 + n]);
                accv = fmaf(h[j], Cs[t*64 + n], accv);
            }
            accv += __shfl_down_sync(0xffffffffu, accv, 4, 8);
            accv += __shfl_down_sync(0xffffffffu, accv, 2, 8);
            accv += __shfl_down_sync(0xffffffffu, accv, 1, 8);
            if (ng == 0) {
                float yv = accv + us[t*32 + dl] * Dd;
                float z = zs[t*32 + dl];
                yv *= z / (1.f + __expf(-z));
                ysm[t*32 + dl] = yv;
            }
        }
        __syncthreads();
#pragma unroll
        for (int j = 0; j < 4; j++) {
            int e = tid + j * 256;
            int t = e >> 5;
            int dd = e & 31;
            g_y[(size_t)(b*Tt + tbase + t) * DIdim + d0 + dd] = ysm[t*32 + dd];
        }
        __syncthreads();
    }
}

// ---------------- layernorm + film + residual --------------------------------
__global__ __launch_bounds__(256) void ln_film_kernel(
    const float* __restrict__ lnw, const float* __restrict__ lnb,
    const float* __restrict__ fg, const float* __restrict__ fb,
    float* __restrict__ extOut, int toX)
{
    const int m = blockIdx.x;
    const int tid = threadIdx.x;
    const float* row = g_h + (size_t)m * DMdim;

    __shared__ float red[8];
    __shared__ float stats[2];

    float v[3];
    float s = 0.f;
#pragma unroll
    for (int j = 0; j < 3; j++) { v[j] = row[tid + j*256]; s += v[j]; }
#pragma unroll
    for (int o = 16; o > 0; o >>= 1) s += __shfl_down_sync(0xffffffffu, s, o);
    if ((tid & 31) == 0) red[tid >> 5] = s;
    __syncthreads();
    if (tid == 0) {
        float tot = 0.f;
        for (int i = 0; i < 8; i++) tot += red[i];
        stats[0] = tot;
    }
    __syncthreads();
    const float mean = stats[0] * (1.f / DMdim);

    float s2 = 0.f;
#pragma unroll
    for (int j = 0; j < 3; j++) { float dd = v[j] - mean; s2 += dd*dd; }
#pragma unroll
    for (int o = 16; o > 0; o >>= 1) s2 += __shfl_down_sync(0xffffffffu, s2, o);
    if ((tid & 31) == 0) red[tid >> 5] = s2;
    __syncthreads();
    if (tid == 0) {
        float tot = 0.f;
        for (int i = 0; i < 8; i++) tot += red[i];
        stats[1] = tot;
    }
    __syncthreads();
    const float rstd = rsqrtf(stats[1] * (1.f / DMdim) + 1e-5f);

    float* outp = toX ? g_x : extOut;
#pragma unroll
    for (int j = 0; j < 3; j++) {
        int c = tid + j*256;
        size_t gi = (size_t)m * DMdim + c;
        float hn = (v[j] - mean) * rstd * lnw[c] + lnb[c];
        outp[gi] = fg[gi] * hn + fb[gi] + g_x[gi];
    }
}

// ---------------- driver ------------------------------------------------------
extern "C" void kernel_launch(void* const* d_in, const int* in_sizes, int n_in,
                              void* d_out, int out_size)
{
    const float* x    = (const float*)d_in[0];
    const float* mask = (const float*)d_in[1];
    const float* fg   = (const float*)d_in[2];
    const float* fb   = (const float*)d_in[3];
    const float* Win  = (const float*)d_in[4];
    const float* cw   = (const float*)d_in[5];
    const float* cb   = (const float*)d_in[6];
    const float* Wx   = (const float*)d_in[7];
    const float* Wdt  = (const float*)d_in[8];
    const float* bdt  = (const float*)d_in[9];
    const float* Alog = (const float*)d_in[10];
    const float* Dv   = (const float*)d_in[11];
    const float* Wout = (const float*)d_in[12];
    const float* lnw  = (const float*)d_in[13];
    const float* lnb  = (const float*)d_in[14];
    float* out = (float*)d_out;

    mask_kernel<<<(MM*DMdim + 255)/256, 256>>>(x, mask);

    for (int i = 0; i < 2; i++) {
        const float* Win_i  = Win  + (size_t)i * (2*DIdim) * DMdim;
        const float* cw_i   = cw   + (size_t)i * DIdim * DCv;
        const float* cb_i   = cb   + (size_t)i * DIdim;
        const float* Wx_i   = Wx   + (size_t)i * PROJW * DIdim;
        const float* Wdt_i  = Wdt  + (size_t)i * DIdim * Rr;
        const float* bdt_i  = bdt  + (size_t)i * DIdim;
        const float* Alog_i = Alog + (size_t)i * DIdim * Nn;
        const float* Dv_i   = Dv   + (size_t)i * DIdim;
        const float* Wout_i = Wout + (size_t)i * DMdim * DIdim;
        const float* lnw_i  = lnw  + (size_t)i * DMdim;
        const float* lnb_i  = lnb  + (size_t)i * DMdim;
        const float* fg_i   = fg   + (size_t)i * MM * DMdim;
        const float* fb_i   = fb   + (size_t)i * MM * DMdim;

        // in_proj: (8192,768) x (3072,768)^T -> (8192,3072)   [HMMA]
        tgemm_kernel<<<dim3((2*DIdim)/128, MM/128), 256>>>(
            BUF_X, DMdim, Win_i, DMdim, BUF_XZ, 2*DIdim, 2*DIdim, DMdim);

        conv_silu_kernel<<<(MM*DIdim + 255)/256, 256>>>(cw_i, cb_i);

        // x_proj: (8192,1536) x (176,1536)^T -> (8192,176)    [HMMA]
        tgemm_kernel<<<dim3((PROJW + 127)/128, MM/128), 256>>>(
            BUF_UC, DIdim, Wx_i, DIdim, BUF_PROJ, PROJW, PROJW, DIdim);

        // dt_proj + softplus: (8192,48) x (1536,48)^T -> (8192,1536)  [fp32]
        sgemm_kernel<<<dim3(DIdim/BNt, MM/BMt), 256>>>(
            BUF_PROJ, PROJW, Wdt_i, Rr, BUF_DELTA, DIdim, MM, DIdim, Rr, bdt_i, 1);

        scan_kernel<<<dim3(DIdim/32, Bb), 256>>>(Alog_i, Dv_i);

        // out_proj: (8192,1536) x (768,1536)^T -> (8192,768)  [HMMA]
        tgemm_kernel<<<dim3(DMdim/128, MM/128), 256>>>(
            BUF_Y, DIdim, Wout_i, DIdim, BUF_H, DMdim, DMdim, DIdim);

        ln_film_kernel<<<MM, 256>>>(lnw_i, lnb_i, fg_i, fb_i, out, (i == 1) ? 0 : 1);
    }
}